// round 1
// baseline (speedup 1.0000x reference)
#include <cuda_runtime.h>

#define L      2048
#define BATCH  512
#define NDIM   128

#define TT 64   // t-tile
#define BB 64   // batch-tile
#define TS 64   // s-tile

// Scratch (allocation-free rule: __device__ globals)
__device__ double g_T[2][NDIM * NDIM];   // (A^m)^T ping-pong, fp64
__device__ double g_V[L * NDIM];         // v_k = A^k C, fp64
__device__ float  g_h[L];                // impulse response h_k = B . v_k

// ---------------------------------------------------------------------------
// h-pipeline kernels (fp64, repeated doubling)
// ---------------------------------------------------------------------------

__global__ void init_kernel(const float* __restrict__ A, const float* __restrict__ C)
{
    int idx = blockIdx.x * blockDim.x + threadIdx.x;   // 64 * 256 = 16384
    if (idx < NDIM * NDIM) {
        int i = idx / NDIM, j = idx % NDIM;
        g_T[0][j * NDIM + i] = (double)A[i * NDIM + j];  // T = A^T
    }
    if (idx < NDIM)
        g_V[idx] = (double)C[idx];                       // v_0 = C
}

// V[m+j] = A^m @ V[j]  for j in [0, m).  blockIdx.x = j, threadIdx.x = i.
// v_next[i] = sum_k A^m[i][k] v[k] = sum_k T[k*NDIM + i] * v[k]  (coalesced T reads)
__global__ void expand_kernel(int m, int cur)
{
    __shared__ double vs[NDIM];
    const int j = blockIdx.x;
    const int i = threadIdx.x;
    vs[i] = g_V[j * NDIM + i];
    __syncthreads();
    const double* __restrict__ T = g_T[cur];
    double a0 = 0.0, a1 = 0.0, a2 = 0.0, a3 = 0.0;
#pragma unroll 8
    for (int k = 0; k < NDIM; k += 4) {
        a0 += T[(k + 0) * NDIM + i] * vs[k + 0];
        a1 += T[(k + 1) * NDIM + i] * vs[k + 1];
        a2 += T[(k + 2) * NDIM + i] * vs[k + 2];
        a3 += T[(k + 3) * NDIM + i] * vs[k + 3];
    }
    g_V[(m + j) * NDIM + i] = (a0 + a1) + (a2 + a3);
}

// T_{2m} = T_m @ T_m   (since (A^m A^m)^T = (A^T)^m (A^T)^m)
// blockIdx.x = row r, threadIdx.x = col c.
__global__ void square_kernel(int cur)
{
    __shared__ double rs[NDIM];
    const int r = blockIdx.x;
    const int c = threadIdx.x;
    const double* __restrict__ T = g_T[cur];
    rs[c] = T[r * NDIM + c];
    __syncthreads();
    double a0 = 0.0, a1 = 0.0, a2 = 0.0, a3 = 0.0;
#pragma unroll 8
    for (int k = 0; k < NDIM; k += 4) {
        a0 += rs[k + 0] * T[(k + 0) * NDIM + c];
        a1 += rs[k + 1] * T[(k + 1) * NDIM + c];
        a2 += rs[k + 2] * T[(k + 2) * NDIM + c];
        a3 += rs[k + 3] * T[(k + 3) * NDIM + c];
    }
    g_T[cur ^ 1][r * NDIM + c] = (a0 + a1) + (a2 + a3);
}

// h_k = B . v_k  (one block per k, 128-thread reduction)
__global__ void hk_kernel(const float* __restrict__ B)
{
    __shared__ double red[NDIM];
    const int k = blockIdx.x;
    const int i = threadIdx.x;
    double p = (double)B[i] * g_V[k * NDIM + i];
    red[i] = p;
    __syncthreads();
    if (i < 64) red[i] += red[i + 64];
    __syncthreads();
    if (i < 32) {
        double v = red[i] + red[i + 32];
#pragma unroll
        for (int off = 16; off > 0; off >>= 1)
            v += __shfl_down_sync(0xFFFFFFFFu, v, off);
        if (i == 0) g_h[k] = (float)v;
    }
}

// ---------------------------------------------------------------------------
// Causal Toeplitz convolution:
//   out[b,t] = f_t * sum_{s<=t} u[b,s]*h[t-s] + D*u[b,t]
// Tiled as GEMM over (batch-tile 64) x (t-tile 64), looping s-tiles (64).
// 256 threads, 4x4 outputs/thread, rolling 4-register h window.
// ---------------------------------------------------------------------------
__global__ __launch_bounds__(256) void conv_kernel(const float* __restrict__ u,
                                                   const float* __restrict__ Dp,
                                                   float* __restrict__ out)
{
    __shared__ float Us[TS][BB + 1];  // [ss][bb], stride 65 -> conflict-free fill
    __shared__ float hsArr[132];      // hsp = hsArr+4, hsp[-1..126] valid
    float* hsp = hsArr + 4;

    const int tid   = threadIdx.x;
    const int tileT = blockIdx.x;           // 0..31
    const int t0    = tileT * TT;
    const int b0    = blockIdx.y * BB;
    const int tx    = tid & 15;             // t-group
    const int ty    = tid >> 4;             // b-group
    const int tt0   = tx * 4;
    const int bb0   = ty * 4;

    float acc[4][4];
#pragma unroll
    for (int j = 0; j < 4; ++j)
#pragma unroll
        for (int i = 0; i < 4; ++i) acc[j][i] = 0.0f;

    if (tid < 4) hsArr[tid] = 0.0f;  // guards hsp[-4..-1]

    for (int st = 0; st <= tileT; ++st) {
        const int s0 = st * TS;
        __syncthreads();
        // h window for this (t-tile, s-tile): hsp[d] = h[t0-s0-63+d], zero OOB
        if (tid < 128) {
            int g = t0 - s0 - 63 + tid;
            hsp[tid] = (g >= 0 && g < L) ? g_h[g] : 0.0f;
        }
        // u tile: coalesced LDG.32, conflict-free STS (stride 65)
#pragma unroll
        for (int p = 0; p < 16; ++p) {
            int f  = p * 256 + tid;
            int bb = f >> 6;
            int ss = f & 63;
            Us[ss][bb] = u[(size_t)(b0 + bb) * L + (s0 + ss)];
        }
        __syncthreads();

        float w0 = hsp[tt0 + 63];
        float w1 = hsp[tt0 + 64];
        float w2 = hsp[tt0 + 65];
        float w3 = hsp[tt0 + 66];
#pragma unroll 4
        for (int ss = 0; ss < TS; ++ss) {
            float u0 = Us[ss][bb0 + 0];
            float u1 = Us[ss][bb0 + 1];
            float u2 = Us[ss][bb0 + 2];
            float u3 = Us[ss][bb0 + 3];
            acc[0][0] += w0 * u0; acc[0][1] += w0 * u1; acc[0][2] += w0 * u2; acc[0][3] += w0 * u3;
            acc[1][0] += w1 * u0; acc[1][1] += w1 * u1; acc[1][2] += w1 * u2; acc[1][3] += w1 * u3;
            acc[2][0] += w2 * u0; acc[2][1] += w2 * u1; acc[2][2] += w2 * u2; acc[2][3] += w2 * u3;
            acc[3][0] += w3 * u0; acc[3][1] += w3 * u1; acc[3][2] += w3 * u2; acc[3][3] += w3 * u3;
            float nw = hsp[tt0 + 62 - ss];   // hsp[-1] is a zeroed guard slot
            w3 = w2; w2 = w1; w1 = w0; w0 = nw;
        }
    }

    const float Dv = Dp[0];
#pragma unroll
    for (int j = 0; j < 4; ++j) {
        const int t = t0 + tt0 + j;
        const float f = (t == 0) ? 1.0f : 2.0f;
#pragma unroll
        for (int i = 0; i < 4; ++i) {
            const int b = b0 + bb0 + i;
            const size_t off = (size_t)b * L + t;
            out[off] = f * acc[j][i] + Dv * u[off];
        }
    }
}

// ---------------------------------------------------------------------------
extern "C" void kernel_launch(void* const* d_in, const int* in_sizes, int n_in,
                              void* d_out, int out_size)
{
    const float* u  = (const float*)d_in[0];  // (512, 2048)
    const float* A  = (const float*)d_in[1];  // (128, 128)
    const float* B  = (const float*)d_in[2];  // (128,)
    const float* Cd = (const float*)d_in[3];  // (128,)
    const float* Dd = (const float*)d_in[4];  // (1,)
    float* out = (float*)d_out;               // (512, 2048)

    // --- impulse response h[0..L-1] via repeated doubling, fp64 ---
    init_kernel<<<64, 256>>>(A, Cd);
    int cur = 0;
    for (int m = 1; m < L; m <<= 1) {
        expand_kernel<<<m, 128>>>(m, cur);       // fills V[m..2m-1]
        if (2 * m < L) {
            square_kernel<<<128, 128>>>(cur);    // T_{2m} = T_m T_m
            cur ^= 1;
        }
    }
    hk_kernel<<<L, 128>>>(B);

    // --- causal convolution + D*u ---
    dim3 grid(L / TT, BATCH / BB);               // (32, 8)
    conv_kernel<<<grid, 256>>>(u, Dd, out);
}

// round 2
// speedup vs baseline: 1.5827x; 1.5827x over previous
#include <cuda_runtime.h>

#define L      2048
#define BATCH  512
#define NDIM   128

#define TT 64   // t-tile
#define BB 64   // batch-tile
#define TS 64   // s-tile
#define USTRIDE 68  // padded s-stride (16B-aligned rows, conflict-free)

// ---------------- scratch (__device__ globals, allocation-free) ----------------
__device__ double g_S[2][NDIM * NDIM];   // S_k = A^(2^k), row-major, ping-pong
__device__ double g_R[2][NDIM * NDIM];   // R_k = (A^64)^(2^k) TRANSPOSED, ping-pong
__device__ double g_W[64 * NDIM];        // w_j = (A^T)^j B
__device__ double g_Y[32 * NDIM];        // y_i = (A^64)^i C
__device__ float  g_h[L];                // h_k = B A^k C

// ---------------------------------------------------------------------------
__global__ void init_kernel(const float* __restrict__ A,
                            const float* __restrict__ B,
                            const float* __restrict__ C)
{
    int idx = blockIdx.x * blockDim.x + threadIdx.x;   // 64*256 = 16384
    if (idx < NDIM * NDIM) g_S[0][idx] = (double)A[idx];
    if (idx < NDIM) { g_W[idx] = (double)B[idx]; g_Y[idx] = (double)C[idx]; }
}

// Stage k of W phase (k=0..5), one launch, grid = 128 + 2^k blocks of 128 thr:
//   blocks [0,128): squaring  S_{k+1} = S_k * S_k  (k==5: write transposed -> R_0)
//   blocks [128,..): expand   w_{2^k + j} = (A^T)^{2^k} w_j   (reads S_k)
__global__ void stageW_kernel(int k, int cur)
{
    __shared__ double sh[NDIM];
    const double* __restrict__ S = g_S[cur];
    if (blockIdx.x < 128) {                    // ---- squaring ----
        const int r = blockIdx.x, c = threadIdx.x;
        sh[c] = S[r * NDIM + c];
        __syncthreads();
        double a0 = 0, a1 = 0, a2 = 0, a3 = 0;
#pragma unroll 8
        for (int kk = 0; kk < NDIM; kk += 4) {
            a0 += sh[kk + 0] * S[(kk + 0) * NDIM + c];
            a1 += sh[kk + 1] * S[(kk + 1) * NDIM + c];
            a2 += sh[kk + 2] * S[(kk + 2) * NDIM + c];
            a3 += sh[kk + 3] * S[(kk + 3) * NDIM + c];
        }
        double acc = (a0 + a1) + (a2 + a3);
        if (k == 5) g_R[0][c * NDIM + r] = acc;          // R_0 = (A^64)^T
        else        g_S[cur ^ 1][r * NDIM + c] = acc;
    } else {                                   // ---- expand W ----
        const int j = blockIdx.x - 128;
        const int i = threadIdx.x;
        const int m = 1 << k;
        sh[i] = g_W[j * NDIM + i];
        __syncthreads();
        double a0 = 0, a1 = 0, a2 = 0, a3 = 0;
#pragma unroll 8
        for (int c = 0; c < NDIM; c += 4) {
            a0 += S[(c + 0) * NDIM + i] * sh[c + 0];   // (A^T)^m [i][c] = S_k[c][i]
            a1 += S[(c + 1) * NDIM + i] * sh[c + 1];
            a2 += S[(c + 2) * NDIM + i] * sh[c + 2];
            a3 += S[(c + 3) * NDIM + i] * sh[c + 3];
        }
        g_W[(m + j) * NDIM + i] = (a0 + a1) + (a2 + a3);
    }
}

// Stage k of Y phase (k=0..4):
//   k<4 : grid = 128 + 2^k ; blocks [0,128) square R, rest expand Y
//   k==4: grid = 16 ; all blocks expand
__global__ void stageY_kernel(int k, int cur)
{
    __shared__ double sh[NDIM];
    const double* __restrict__ R = g_R[cur];
    if (k < 4 && blockIdx.x < 128) {           // ---- squaring (transposed space) ----
        const int r = blockIdx.x, c = threadIdx.x;
        sh[c] = R[r * NDIM + c];
        __syncthreads();
        double a0 = 0, a1 = 0, a2 = 0, a3 = 0;
#pragma unroll 8
        for (int kk = 0; kk < NDIM; kk += 4) {
            a0 += sh[kk + 0] * R[(kk + 0) * NDIM + c];
            a1 += sh[kk + 1] * R[(kk + 1) * NDIM + c];
            a2 += sh[kk + 2] * R[(kk + 2) * NDIM + c];
            a3 += sh[kk + 3] * R[(kk + 3) * NDIM + c];
        }
        g_R[cur ^ 1][r * NDIM + c] = (a0 + a1) + (a2 + a3);
    } else {                                   // ---- expand Y ----
        const int j = (k < 4) ? (int)blockIdx.x - 128 : (int)blockIdx.x;
        const int i = threadIdx.x;
        const int m = 1 << k;
        sh[i] = g_Y[j * NDIM + i];
        __syncthreads();
        double a0 = 0, a1 = 0, a2 = 0, a3 = 0;
#pragma unroll 8
        for (int c = 0; c < NDIM; c += 4) {
            a0 += R[(c + 0) * NDIM + i] * sh[c + 0];   // M^m [i][c] = R_k[c][i]
            a1 += R[(c + 1) * NDIM + i] * sh[c + 1];
            a2 += R[(c + 2) * NDIM + i] * sh[c + 2];
            a3 += R[(c + 3) * NDIM + i] * sh[c + 3];
        }
        g_Y[(m + j) * NDIM + i] = (a0 + a1) + (a2 + a3);
    }
}

// h[64*i + j] = w_j . y_i   (block = i, 256 threads, 4 lanes per dot)
__global__ void hdot_kernel()
{
    __shared__ double ys[NDIM];
    const int i = blockIdx.x;
    const int tid = threadIdx.x;
    if (tid < NDIM) ys[tid] = g_Y[i * NDIM + tid];
    __syncthreads();
    const int j = tid >> 2, q = tid & 3;
    const double* __restrict__ w = &g_W[j * NDIM + q * 32];
    const double* __restrict__ y = &ys[q * 32];
    double p = 0;
#pragma unroll 8
    for (int c = 0; c < 32; ++c) p += w[c] * y[c];
    p += __shfl_xor_sync(0xFFFFFFFFu, p, 1);
    p += __shfl_xor_sync(0xFFFFFFFFu, p, 2);
    if (q == 0) g_h[i * 64 + j] = (float)p;
}

// ---------------------------------------------------------------------------
// Causal Toeplitz conv: out[b,t] = f_t * sum_{s<=t} h[t-s] u[b,s] + D u[b,t]
// 128 threads/block, 8t x 4b per thread, heaviest tiles scheduled first.
// ---------------------------------------------------------------------------
__global__ __launch_bounds__(128) void conv_kernel(const float* __restrict__ u,
                                                   const float* __restrict__ Dp,
                                                   float* __restrict__ out)
{
    __shared__ float Us[BB][USTRIDE];   // [bb][ss], USTRIDE=68
    __shared__ float hsArr[132];
    float* hsp = hsArr + 4;

    const int z     = blockIdx.x;
    const int tileT = 31 - (z >> 3);        // heaviest (tileT=31) first
    const int t0    = tileT * TT;
    const int b0    = (z & 7) * BB;
    const int tid   = threadIdx.x;
    const int tx    = tid & 7;              // 8 t-groups
    const int ty    = tid >> 3;             // 16 b-groups
    const int tt0   = tx * 8;
    const int bb0   = ty * 4;

    float acc[8][4];
#pragma unroll
    for (int r = 0; r < 8; ++r)
#pragma unroll
        for (int q = 0; q < 4; ++q) acc[r][q] = 0.0f;

    if (tid < 4) hsArr[tid] = 0.0f;

    for (int st = 0; st <= tileT; ++st) {
        const int s0 = st * TS;
        __syncthreads();
        // h window: hsp[d] = h[t0-s0-63+d], zero OOB
        {
            int g = t0 - s0 - 63 + tid;
            hsp[tid] = (g >= 0 && g < L) ? g_h[g] : 0.0f;
        }
        // u tile: float4 loads, [bb][ss] layout
#pragma unroll
        for (int p = 0; p < 8; ++p) {
            int f4 = p * 128 + tid;
            int e  = f4 * 4;
            int bb = e >> 6;
            int ss = e & 63;
            float4 v = *(const float4*)&u[(size_t)(b0 + bb) * L + (s0 + ss)];
            *(float4*)&Us[bb][ss] = v;
        }
        __syncthreads();

        float w[8];
#pragma unroll
        for (int r = 0; r < 8; ++r) w[r] = hsp[tt0 + 63 + r];

#pragma unroll 8
        for (int ss = 0; ss < TS; ++ss) {
            float u0 = Us[bb0 + 0][ss];
            float u1 = Us[bb0 + 1][ss];
            float u2 = Us[bb0 + 2][ss];
            float u3 = Us[bb0 + 3][ss];
#pragma unroll
            for (int r = 0; r < 8; ++r) {
                acc[r][0] += w[r] * u0;
                acc[r][1] += w[r] * u1;
                acc[r][2] += w[r] * u2;
                acc[r][3] += w[r] * u3;
            }
            float nw = hsp[tt0 + 62 - ss];   // hsp[-1] is zeroed guard
#pragma unroll
            for (int r = 7; r > 0; --r) w[r] = w[r - 1];
            w[0] = nw;
        }
    }

    const float Dv = Dp[0];
#pragma unroll
    for (int r = 0; r < 8; ++r) {
        const int t = t0 + tt0 + r;
        const float f = (t == 0) ? 1.0f : 2.0f;
#pragma unroll
        for (int q = 0; q < 4; ++q) {
            const size_t off = (size_t)(b0 + bb0 + q) * L + t;
            out[off] = f * acc[r][q] + Dv * u[off];
        }
    }
}

// ---------------------------------------------------------------------------
extern "C" void kernel_launch(void* const* d_in, const int* in_sizes, int n_in,
                              void* d_out, int out_size)
{
    const float* u  = (const float*)d_in[0];  // (512, 2048)
    const float* A  = (const float*)d_in[1];  // (128, 128)
    const float* B  = (const float*)d_in[2];  // (128,)
    const float* Cd = (const float*)d_in[3];  // (128,)
    const float* Dd = (const float*)d_in[4];  // (1,)
    float* out = (float*)d_out;               // (512, 2048)

    init_kernel<<<64, 256>>>(A, B, Cd);

    int cs = 0;
    for (int k = 0; k <= 5; ++k) {
        stageW_kernel<<<128 + (1 << k), 128>>>(k, cs);
        if (k < 5) cs ^= 1;
    }
    int cr = 0;
    for (int k = 0; k <= 4; ++k) {
        int grid = (k < 4) ? 128 + (1 << k) : (1 << k);
        stageY_kernel<<<grid, 128>>>(k, cr);
        if (k < 4) cr ^= 1;
    }
    hdot_kernel<<<32, 256>>>();

    conv_kernel<<<256, 128>>>(u, Dd, out);
}